// round 1
// baseline (speedup 1.0000x reference)
#include <cuda_runtime.h>

// 3-layer MLP: out = (relu(relu(x@w1+b1)@w2+b2))@w3+b3
// Baseline: SIMT fp32 tiled GEMM, 128x128x16 tiles, 8x8 per-thread register
// blocking, double-buffered shared memory with register prefetch.
// Intermediates h1/h2 live in __device__ global scratch (no allocations).

constexpr int BM = 128;
constexpr int BN = 128;
constexpr int BK = 16;
constexpr int TM = 8;
constexpr int TN = 8;

constexpr int BATCH = 4096;
constexpr int IN    = 2048;
constexpr int HID   = 4096;
constexpr int NCLS  = 1000;

__device__ float g_h1[(size_t)BATCH * HID];
__device__ float g_h2[(size_t)BATCH * HID];

__global__ __launch_bounds__(256)
void gemm_bias_act_kernel(const float* __restrict__ A,   // [M,K] row-major
                          const float* __restrict__ B,   // [K,N] row-major
                          const float* __restrict__ bias,// [N]
                          float* __restrict__ C,         // [M,N]
                          int M, int N, int K, int do_relu)
{
    __shared__ float As[2][BK][BM];   // transposed A tile
    __shared__ float Bs[2][BK][BN];

    const int tid = threadIdx.x;
    const int bx = blockIdx.x;        // N tiles
    const int by = blockIdx.y;        // M tiles

    // 16x16 thread grid, each thread owns an 8x8 output sub-tile
    const int trow = tid >> 4;        // 0..15
    const int tcol = tid & 15;        // 0..15
    const int row0 = by * BM + trow * TM;
    const int col0 = bx * BN + tcol * TN;

    // global-load assignment: each thread loads 8 consecutive floats of A
    // (one row segment) and 8 consecutive floats of B.
    const int arow = tid >> 1;          // 0..127
    const int acol = (tid & 1) * 8;     // 0 or 8
    const int brow = tid >> 4;          // 0..15
    const int bcol = (tid & 15) * 8;    // 0..120

    const int ktiles = K / BK;

    float acc[TM][TN];
#pragma unroll
    for (int i = 0; i < TM; i++)
#pragma unroll
        for (int j = 0; j < TN; j++) acc[i][j] = 0.f;

    const float* Ag = A + (size_t)(by * BM + arow) * K + acol;
    const int bgcol = bx * BN + bcol;            // N%8==0 for all layers
    const bool bok = (bgcol < N);

    float4 ra0, ra1, rb0, rb1;
    rb0 = make_float4(0.f, 0.f, 0.f, 0.f);
    rb1 = make_float4(0.f, 0.f, 0.f, 0.f);

#define STORE_TILE(bufi)                                                     \
    do {                                                                     \
        As[bufi][acol + 0][arow] = ra0.x;                                    \
        As[bufi][acol + 1][arow] = ra0.y;                                    \
        As[bufi][acol + 2][arow] = ra0.z;                                    \
        As[bufi][acol + 3][arow] = ra0.w;                                    \
        As[bufi][acol + 4][arow] = ra1.x;                                    \
        As[bufi][acol + 5][arow] = ra1.y;                                    \
        As[bufi][acol + 6][arow] = ra1.z;                                    \
        As[bufi][acol + 7][arow] = ra1.w;                                    \
        *(float4*)&Bs[bufi][brow][bcol]     = rb0;                           \
        *(float4*)&Bs[bufi][brow][bcol + 4] = rb1;                           \
    } while (0)

    // prologue: tile 0
    {
        const float* ap = Ag;
        ra0 = *(const float4*)(ap);
        ra1 = *(const float4*)(ap + 4);
        if (bok) {
            const float* bp = B + (size_t)brow * N + bgcol;
            rb0 = *(const float4*)(bp);
            rb1 = *(const float4*)(bp + 4);
        }
        STORE_TILE(0);
    }
    __syncthreads();

    for (int kt = 0; kt < ktiles; kt++) {
        const int buf = kt & 1;

        // prefetch next tile into registers (overlaps with compute below)
        if (kt + 1 < ktiles) {
            const float* ap = Ag + (size_t)(kt + 1) * BK;
            ra0 = *(const float4*)(ap);
            ra1 = *(const float4*)(ap + 4);
            if (bok) {
                const float* bp = B + (size_t)((kt + 1) * BK + brow) * N + bgcol;
                rb0 = *(const float4*)(bp);
                rb1 = *(const float4*)(bp + 4);
            }
        }

#pragma unroll
        for (int k = 0; k < BK; k++) {
            float a[TM], b[TN];
            *(float4*)&a[0] = *(const float4*)&As[buf][k][trow * TM];
            *(float4*)&a[4] = *(const float4*)&As[buf][k][trow * TM + 4];
            *(float4*)&b[0] = *(const float4*)&Bs[buf][k][tcol * TN];
            *(float4*)&b[4] = *(const float4*)&Bs[buf][k][tcol * TN + 4];
#pragma unroll
            for (int i = 0; i < TM; i++)
#pragma unroll
                for (int j = 0; j < TN; j++)
                    acc[i][j] = fmaf(a[i], b[j], acc[i][j]);
        }

        if (kt + 1 < ktiles) {
            const int nb = buf ^ 1;
            STORE_TILE(nb);
        }
        __syncthreads();
    }
#undef STORE_TILE

    // epilogue: bias + optional relu; M is always a multiple of BM, so only
    // the N dimension needs predication (layer 3, N=1000).
#pragma unroll
    for (int i = 0; i < TM; i++) {
        const int r = row0 + i;
#pragma unroll
        for (int j = 0; j < TN; j++) {
            const int c = col0 + j;
            if (c < N) {
                float v = acc[i][j] + bias[c];
                if (do_relu) v = fmaxf(v, 0.f);
                C[(size_t)r * N + c] = v;
            }
        }
    }
}

extern "C" void kernel_launch(void* const* d_in, const int* in_sizes, int n_in,
                              void* d_out, int out_size)
{
    (void)in_sizes; (void)n_in; (void)out_size;
    const float* x  = (const float*)d_in[0];
    const float* w1 = (const float*)d_in[1];
    const float* b1 = (const float*)d_in[2];
    const float* w2 = (const float*)d_in[3];
    const float* b2 = (const float*)d_in[4];
    const float* w3 = (const float*)d_in[5];
    const float* b3 = (const float*)d_in[6];
    float* out = (float*)d_out;

    float *h1 = nullptr, *h2 = nullptr;
    cudaGetSymbolAddress((void**)&h1, g_h1);
    cudaGetSymbolAddress((void**)&h2, g_h2);

    dim3 blk(256);
    gemm_bias_act_kernel<<<dim3(HID / BN, BATCH / BM), blk>>>(
        x, w1, b1, h1, BATCH, HID, IN, 1);
    gemm_bias_act_kernel<<<dim3(HID / BN, BATCH / BM), blk>>>(
        h1, w2, b2, h2, BATCH, HID, HID, 1);
    gemm_bias_act_kernel<<<dim3((NCLS + BN - 1) / BN, BATCH / BM), blk>>>(
        h2, w3, b3, out, BATCH, NCLS, HID, 0);
}

// round 4
// speedup vs baseline: 2.9522x; 2.9522x over previous
#include <cuda_runtime.h>
#include <cstdint>

// ============================================================================
// 3-layer MLP via mma.sync.m16n8k8.tf32 (sm_80+ path; tcgen05 is rejected by
// the harness's compute_103 virtual arch).
//   out = relu(relu(x@w1+b1)@w2+b2)@w3+b3
// CTA tile 128 x BN (BN=256 for layers 1/2, 128 for layer 3), BK=16,
// 8 warps in a 2(M) x 4(N) grid, warp tile 64 x BN/4.
// 4-stage cp.async pipeline; smem rows padded to 20 floats so every mma
// fragment lds.32 is bank-conflict-free (bases 20r mod 32 all distinct).
// Operands pre-rounded to tf32 with cvt.rna (avoids HW truncation bias).
// ============================================================================

#define DINL __device__ __forceinline__

constexpr int BATCH = 4096, IN = 2048, HID = 4096, NCLS = 1000, NCLS_PAD = 1024;

constexpr int BM = 128;
constexpr int BK = 16;            // K per pipeline stage (two k=8 mma steps)
constexpr int STAGES = 4;
constexpr int LDSW = 20;          // smem row stride in floats (16 + 4 pad)
constexpr int A_STAGE = BM * LDSW * 4;            // 10240 B

constexpr int smem_bytes(int BN) { return STAGES * (A_STAGE + BN * LDSW * 4); }

// device scratch (allocation-guard-safe)
__device__ float g_h1 [(size_t)BATCH * HID];
__device__ float g_h2 [(size_t)BATCH * HID];
__device__ float g_xr [(size_t)BATCH * IN];
__device__ float g_w1t[(size_t)HID * IN];
__device__ float g_w2t[(size_t)HID * HID];
__device__ float g_w3t[(size_t)NCLS_PAD * HID];

// ---------------------------------------------------------------- helpers
DINL uint32_t s2u(const void* p) {
    uint32_t a;
    asm("{ .reg .u64 t; cvta.to.shared.u64 t, %1; cvt.u32.u64 %0, t; }"
        : "=r"(a) : "l"(p));
    return a;
}
DINL void cp_async16(uint32_t s, const void* g) {
    asm volatile("cp.async.cg.shared.global [%0], [%1], 16;" :: "r"(s), "l"(g));
}
DINL void cp_commit() { asm volatile("cp.async.commit_group;" ::: "memory"); }
#define CP_WAIT(n) asm volatile("cp.async.wait_group %0;" :: "n"(n) : "memory")

DINL uint32_t lds32(uint32_t a) {
    uint32_t v;
    asm volatile("ld.shared.b32 %0, [%1];" : "=r"(v) : "r"(a));
    return v;
}
DINL float rna_tf32(float x) {
    uint32_t o;
    asm("cvt.rna.tf32.f32 %0, %1;" : "=r"(o) : "f"(x));
    return __uint_as_float(o);
}
DINL void mma1688(float* d, const uint32_t* a, const uint32_t* b) {
    asm volatile(
        "mma.sync.aligned.m16n8k8.row.col.f32.tf32.tf32.f32 "
        "{%0,%1,%2,%3}, {%4,%5,%6,%7}, {%8,%9}, {%0,%1,%2,%3};"
        : "+f"(d[0]), "+f"(d[1]), "+f"(d[2]), "+f"(d[3])
        : "r"(a[0]), "r"(a[1]), "r"(a[2]), "r"(a[3]), "r"(b[0]), "r"(b[1]));
}

// ------------------------------------------------------------------ GEMM
// A [M,K] row-major (tf32-rounded), Bt [Npad,K] row-major (= B^T, rounded),
// C [M,N].  flags: bit0 = relu, bit1 = rna-round stored output.
template <int BN>
__global__ __launch_bounds__(256, 1)
void mlp_gemm_mma(const float* __restrict__ A, const float* __restrict__ Bt,
                  const float* __restrict__ bias, float* __restrict__ C,
                  int K, int N, int flags) {
    constexpr int WN = BN / 4;          // warp tile N (warp tile M = 64)
    constexpr int NF = WN / 8;          // n fragments per warp
    constexpr int MF = 4;               // m fragments per warp (64/16)
    constexpr int B_STAGE = BN * LDSW * 4;
    constexpr int B_OFF = STAGES * A_STAGE;

    extern __shared__ char smem[];
    const uint32_t sb = s2u(smem);
    const int tid = threadIdx.x;
    const int wid = tid >> 5, lid = tid & 31;
    const int warp_m = wid & 1;         // 0..1
    const int warp_n = wid >> 1;        // 0..3
    const int m0 = blockIdx.x * BM;
    const int n0 = blockIdx.y * BN;

    const int lg = lid >> 2;            // group id (0..7)
    const int lc = lid & 3;             // id in group (0..3)

    const float* Ag = A + (size_t)m0 * K;
    const float* Bg = Bt + (size_t)n0 * K;

    // ---- stage loader: 16B chunks, smem rows padded to LDSW floats
    auto load_stage = [&](int buf, int kt) {
        const uint32_t abase = sb + buf * A_STAGE;
        const float* ap = Ag + kt * BK;
#pragma unroll
        for (int t = 0; t < (BM * 4) / 256; t++) {
            int ch = tid + t * 256;
            int row = ch >> 2, j = ch & 3;
            cp_async16(abase + (row * LDSW + j * 4) * 4,
                       ap + (size_t)row * K + j * 4);
        }
        const uint32_t bbase = sb + B_OFF + buf * B_STAGE;
        const float* bp = Bg + kt * BK;
#pragma unroll
        for (int t = 0; t < (BN * 4) / 256; t++) {
            int ch = tid + t * 256;
            int row = ch >> 2, j = ch & 3;
            cp_async16(bbase + (row * LDSW + j * 4) * 4,
                       bp + (size_t)row * K + j * 4);
        }
    };

    const int ktiles = K / BK;

    for (int s = 0; s < STAGES - 1; s++) { load_stage(s, s); cp_commit(); }

    float acc[MF][NF][4];
#pragma unroll
    for (int i = 0; i < MF; i++)
#pragma unroll
        for (int j = 0; j < NF; j++)
#pragma unroll
            for (int r = 0; r < 4; r++) acc[i][j][r] = 0.f;

    // per-thread fragment base addresses (buffer 0)
    const uint32_t a_t0 = sb + ((warp_m * 64 + lg) * LDSW + lc) * 4;
    const uint32_t b_t0 = sb + B_OFF + ((warp_n * WN + lg) * LDSW + lc) * 4;

    for (int kt = 0; kt < ktiles; kt++) {
        const int b = kt & (STAGES - 1);
        CP_WAIT(STAGES - 2);
        __syncthreads();   // stage b ready for all; all warps done with kt-1

        const int nk = kt + STAGES - 1;
        if (nk < ktiles) load_stage(nk & (STAGES - 1), nk);
        cp_commit();

        const uint32_t ab = a_t0 + b * A_STAGE;
        const uint32_t bb = b_t0 + b * B_STAGE;
#pragma unroll
        for (int kk = 0; kk < 2; kk++) {
            uint32_t af[MF][4];
#pragma unroll
            for (int mf = 0; mf < MF; mf++) {
                uint32_t base = ab + (mf * 16 * LDSW + kk * 8) * 4;
                af[mf][0] = lds32(base);
                af[mf][1] = lds32(base + 8 * LDSW * 4);
                af[mf][2] = lds32(base + 16);
                af[mf][3] = lds32(base + 8 * LDSW * 4 + 16);
            }
            uint32_t bf[NF][2];
#pragma unroll
            for (int nf = 0; nf < NF; nf++) {
                uint32_t base = bb + (nf * 8 * LDSW + kk * 8) * 4;
                bf[nf][0] = lds32(base);
                bf[nf][1] = lds32(base + 16);
            }
#pragma unroll
            for (int mf = 0; mf < MF; mf++)
#pragma unroll
                for (int nf = 0; nf < NF; nf++)
                    mma1688(acc[mf][nf], af[mf], bf[nf]);
        }
    }

    // ---- epilogue: bias + relu (+ tf32 rna for next layer), direct stores
    const int do_relu = flags & 1, do_rna = flags & 2;
#pragma unroll
    for (int mf = 0; mf < MF; mf++) {
#pragma unroll
        for (int r2 = 0; r2 < 2; r2++) {
            const int m = m0 + warp_m * 64 + mf * 16 + lg + r2 * 8;
            float* crow = C + (size_t)m * N;
#pragma unroll
            for (int nf = 0; nf < NF; nf++) {
                const int c = n0 + warp_n * WN + nf * 8 + lc * 2;
                if (c < N) {                         // N is even everywhere
                    float v0 = acc[mf][nf][r2 * 2 + 0] + __ldg(bias + c);
                    float v1 = acc[mf][nf][r2 * 2 + 1] + __ldg(bias + c + 1);
                    if (do_relu) { v0 = fmaxf(v0, 0.f); v1 = fmaxf(v1, 0.f); }
                    if (do_rna)  { v0 = rna_tf32(v0);  v1 = rna_tf32(v1); }
                    float2 v = make_float2(v0, v1);
                    *(float2*)(crow + c) = v;
                }
            }
        }
    }
}

// ------------------------------------------------- prep kernels (per launch)
__global__ void transpose_rna(const float* __restrict__ s, float* __restrict__ d,
                              int R, int C, int Cpad) {
    __shared__ float t[32][33];
    const int c0 = blockIdx.x * 32, r0 = blockIdx.y * 32;
    const int x = threadIdx.x, y = threadIdx.y;
#pragma unroll
    for (int i = y; i < 32; i += 8) {
        int r = r0 + i, c = c0 + x;
        t[i][x] = (c < C) ? s[(size_t)r * C + c] : 0.f;   // R always tile-exact
    }
    __syncthreads();
#pragma unroll
    for (int i = y; i < 32; i += 8) {
        int cc = c0 + i, rr = r0 + x;
        if (cc < Cpad) d[(size_t)cc * R + rr] = rna_tf32(t[x][i]);
    }
}

__global__ void rna_copy4(const float4* __restrict__ s, float4* __restrict__ d,
                          int n4) {
    int i = blockIdx.x * blockDim.x + threadIdx.x;
    if (i < n4) {
        float4 v = s[i];
        v.x = rna_tf32(v.x); v.y = rna_tf32(v.y);
        v.z = rna_tf32(v.z); v.w = rna_tf32(v.w);
        d[i] = v;
    }
}

// ----------------------------------------------------------------- launcher
extern "C" void kernel_launch(void* const* d_in, const int* in_sizes, int n_in,
                              void* d_out, int out_size) {
    (void)in_sizes; (void)n_in; (void)out_size;
    const float* x  = (const float*)d_in[0];
    const float* w1 = (const float*)d_in[1];
    const float* b1 = (const float*)d_in[2];
    const float* w2 = (const float*)d_in[3];
    const float* b2 = (const float*)d_in[4];
    const float* w3 = (const float*)d_in[5];
    const float* b3 = (const float*)d_in[6];
    float* out = (float*)d_out;

    float *h1, *h2, *xr, *w1t, *w2t, *w3t;
    cudaGetSymbolAddress((void**)&h1,  g_h1);
    cudaGetSymbolAddress((void**)&h2,  g_h2);
    cudaGetSymbolAddress((void**)&xr,  g_xr);
    cudaGetSymbolAddress((void**)&w1t, g_w1t);
    cudaGetSymbolAddress((void**)&w2t, g_w2t);
    cudaGetSymbolAddress((void**)&w3t, g_w3t);

    cudaFuncSetAttribute(mlp_gemm_mma<256>,
                         cudaFuncAttributeMaxDynamicSharedMemorySize,
                         smem_bytes(256));
    cudaFuncSetAttribute(mlp_gemm_mma<128>,
                         cudaFuncAttributeMaxDynamicSharedMemorySize,
                         smem_bytes(128));

    dim3 tb(32, 8);
    transpose_rna<<<dim3(HID / 32, IN / 32), tb>>>(w1, w1t, IN, HID, HID);
    transpose_rna<<<dim3(HID / 32, HID / 32), tb>>>(w2, w2t, HID, HID, HID);
    transpose_rna<<<dim3(NCLS_PAD / 32, HID / 32), tb>>>(w3, w3t, HID, NCLS,
                                                         NCLS_PAD);
    {
        int n4 = BATCH * IN / 4;
        rna_copy4<<<(n4 + 255) / 256, 256>>>((const float4*)x, (float4*)xr, n4);
    }

    // grid.x = M tiles: consecutive CTAs in a wave share the same weight tile
    mlp_gemm_mma<256><<<dim3(BATCH / BM, HID / 256), 256, smem_bytes(256)>>>(
        xr, w1t, b1, h1, IN, HID, /*relu+rna*/ 3);
    mlp_gemm_mma<256><<<dim3(BATCH / BM, HID / 256), 256, smem_bytes(256)>>>(
        h1, w2t, b2, h2, HID, HID, 3);
    mlp_gemm_mma<128><<<dim3(BATCH / BM, NCLS_PAD / 128), 256, smem_bytes(128)>>>(
        h2, w3t, b3, out, HID, NCLS, 0);
}